// round 1
// baseline (speedup 1.0000x reference)
#include <cuda_runtime.h>
#include <cuda_bf16.h>

// HungarianMatcher cost tensor: C[bs, nq, nt] for bs=16, nq=900, nc=256, nt=800.
// Fused single-pass kernel: softmax (inline, per-warp) + class gather + L1 cdist + GIoU.
// HBM-store-bound (46MB output); tile 8 query rows per block to amortize target smem staging.

constexpr int NC      = 256;   // num classes (logits inner dim)
constexpr int NT_MAX  = 800;   // max targets staged in smem
constexpr int TILE_N  = 8;     // query rows per block
constexpr int THREADS = 256;   // 8 warps: one warp per query row for softmax

constexpr float C_CLASS = 1.0f;
constexpr float C_BBOX  = 5.0f;
constexpr float C_GIOU  = 2.0f;
constexpr float EPS     = 1e-7f;

__global__ __launch_bounds__(THREADS)
void matcher_cost_kernel(const float* __restrict__ logits,   // [N, NC]
                         const float* __restrict__ pboxes,   // [N, 4] cxcywh
                         const int*   __restrict__ labels,   // [nt]
                         const float* __restrict__ tboxes,   // [nt, 4] cxcywh
                         float*       __restrict__ out,      // [N, nt]
                         int n_rows, int nt)
{
    __shared__ float  s_prob[TILE_N][NC];   // softmax probs, 8KB
    __shared__ float4 s_tc[NT_MAX];         // tgt cxcywh       12.8KB
    __shared__ float4 s_tx[NT_MAX];         // tgt xyxy         12.8KB
    __shared__ float  s_tarea[NT_MAX];      //                   3.2KB
    __shared__ int    s_tlab[NT_MAX];       //                   3.2KB
    __shared__ float4 s_pc[TILE_N];         // pred cxcywh
    __shared__ float4 s_px[TILE_N];         // pred xyxy
    __shared__ float  s_parea[TILE_N];

    const int tid = threadIdx.x;
    const int n0  = blockIdx.x * TILE_N;

    // --- Stage target data into smem (once per block) ---
    const float4* tb4 = reinterpret_cast<const float4*>(tboxes);
    for (int m = tid; m < nt; m += THREADS) {
        float4 b = tb4[m];
        s_tc[m] = b;
        float x0 = b.x - 0.5f * b.z, y0 = b.y - 0.5f * b.w;
        float x1 = b.x + 0.5f * b.z, y1 = b.y + 0.5f * b.w;
        s_tx[m]    = make_float4(x0, y0, x1, y1);
        s_tarea[m] = (x1 - x0) * (y1 - y0);
        s_tlab[m]  = labels[m];
    }

    // --- Inline softmax: warp w owns query row n0+w (NC=256 -> 8 vals/lane) ---
    const int warp = tid >> 5, lane = tid & 31;
    const int n = n0 + warp;
    if (n < n_rows) {
        const float* lr = logits + (size_t)n * NC;
        float v[NC / 32];
        float mx = -1e30f;
        #pragma unroll
        for (int i = 0; i < NC / 32; i++) {
            v[i] = lr[lane + 32 * i];
            mx = fmaxf(mx, v[i]);
        }
        #pragma unroll
        for (int o = 16; o > 0; o >>= 1)
            mx = fmaxf(mx, __shfl_xor_sync(0xffffffffu, mx, o));
        float sum = 0.0f;
        #pragma unroll
        for (int i = 0; i < NC / 32; i++) {
            v[i] = expf(v[i] - mx);
            sum += v[i];
        }
        #pragma unroll
        for (int o = 16; o > 0; o >>= 1)
            sum += __shfl_xor_sync(0xffffffffu, sum, o);
        float inv = 1.0f / sum;
        #pragma unroll
        for (int i = 0; i < NC / 32; i++)
            s_prob[warp][lane + 32 * i] = v[i] * inv;

        if (lane == 0) {
            float4 b = reinterpret_cast<const float4*>(pboxes)[n];
            s_pc[warp] = b;
            float x0 = b.x - 0.5f * b.z, y0 = b.y - 0.5f * b.w;
            float x1 = b.x + 0.5f * b.z, y1 = b.y + 0.5f * b.w;
            s_px[warp]    = make_float4(x0, y0, x1, y1);
            s_parea[warp] = (x1 - x0) * (y1 - y0);
        }
    }
    __syncthreads();

    // --- Main pairwise loop: thread <-> target m, inner unrolled over 8 rows ---
    for (int m = tid; m < nt; m += THREADS) {
        const float4 tc = s_tc[m];
        const float4 tx = s_tx[m];
        const float  ta = s_tarea[m];
        const int   lab = s_tlab[m];
        #pragma unroll
        for (int i = 0; i < TILE_N; i++) {
            if (n0 + i >= n_rows) break;
            const float4 pc = s_pc[i];
            const float4 px = s_px[i];
            const float  pa = s_parea[i];

            // L1 cdist on cxcywh
            float l1 = fabsf(pc.x - tc.x) + fabsf(pc.y - tc.y)
                     + fabsf(pc.z - tc.z) + fabsf(pc.w - tc.w);

            // IoU on xyxy
            float ltx = fmaxf(px.x, tx.x), lty = fmaxf(px.y, tx.y);
            float rbx = fminf(px.z, tx.z), rby = fminf(px.w, tx.w);
            float inter = fmaxf(rbx - ltx, 0.0f) * fmaxf(rby - lty, 0.0f);
            float uni   = pa + ta - inter;
            float iou   = inter / (uni + EPS);

            // enclosing box
            float ex0 = fminf(px.x, tx.x), ey0 = fminf(px.y, tx.y);
            float ex1 = fmaxf(px.z, tx.z), ey1 = fmaxf(px.w, tx.w);
            float ca  = fmaxf(ex1 - ex0, 0.0f) * fmaxf(ey1 - ey0, 0.0f);
            float giou = iou - (ca - uni) / (ca + EPS);

            float cost = C_BBOX * l1
                       - C_CLASS * s_prob[i][lab]
                       - C_GIOU * giou;
            out[(size_t)(n0 + i) * nt + m] = cost;
        }
    }
}

extern "C" void kernel_launch(void* const* d_in, const int* in_sizes, int n_in,
                              void* d_out, int out_size)
{
    const float* logits = (const float*)d_in[0];   // [16*900, 256]
    const float* pboxes = (const float*)d_in[1];   // [16*900, 4]
    const int*   labels = (const int*)  d_in[2];   // [800]
    const float* tboxes = (const float*)d_in[3];   // [800, 4]
    float*       out    = (float*)d_out;           // [16*900, 800]

    const int n_rows = in_sizes[1] / 4;            // 14400
    const int nt     = in_sizes[2];                // 800

    const int blocks = (n_rows + TILE_N - 1) / TILE_N;
    matcher_cost_kernel<<<blocks, THREADS>>>(logits, pboxes, labels, tboxes,
                                             out, n_rows, nt);
}

// round 3
// speedup vs baseline: 1.9191x; 1.9191x over previous
#include <cuda_runtime.h>
#include <cuda_bf16.h>

// HungarianMatcher cost tensor C[16,900,800], nc=256.
// R2: warp-per-row, float4-vectorized targets/stores, targets stored raw in smem
// (xyxy/area recomputed in regs), fast math divides. Issue-bound optimization.

constexpr int NC      = 256;
constexpr int NT_MAX  = 800;
constexpr int TILE_N  = 8;     // rows per block (one per warp)
constexpr int THREADS = 256;

constexpr float EPS = 1e-7f;

__device__ __forceinline__ float pair_cost(
    float pcx, float pcy, float pw, float ph,
    float px0, float py0, float px1, float py1, float pa,
    float4 t, float prob)
{
    float hw = 0.5f * t.z, hh = 0.5f * t.w;
    float tx0 = t.x - hw, ty0 = t.y - hh;
    float tx1 = t.x + hw, ty1 = t.y + hh;
    float ta  = t.z * t.w;

    float l1 = fabsf(pcx - t.x) + fabsf(pcy - t.y)
             + fabsf(pw  - t.z) + fabsf(ph  - t.w);

    float ix = fminf(px1, tx1) - fmaxf(px0, tx0);
    float iy = fminf(py1, ty1) - fmaxf(py0, ty0);
    float inter = fmaxf(ix, 0.0f) * fmaxf(iy, 0.0f);
    float uni   = pa + ta - inter;
    float iou   = __fdividef(inter, uni + EPS);

    // enclosing box (boxes are valid: rb_c >= lt_c, no clamp needed)
    float cx = fmaxf(px1, tx1) - fminf(px0, tx0);
    float cy = fmaxf(py1, ty1) - fminf(py0, ty0);
    float ca = cx * cy;
    float giou = iou - __fdividef(ca - uni, ca + EPS);

    return 5.0f * l1 - prob - 2.0f * giou;
}

__global__ __launch_bounds__(THREADS, 3)
void matcher_cost_kernel(const float* __restrict__ logits,   // [N, NC]
                         const float* __restrict__ pboxes,   // [N, 4]
                         const int*   __restrict__ labels,   // [nt]
                         const float* __restrict__ tboxes,   // [nt, 4]
                         float*       __restrict__ out,      // [N, nt]
                         int n_rows, int nt)
{
    __shared__ float4 s_t[NT_MAX];          // raw target cxcywh   12.8KB
    __shared__ int    s_lab[NT_MAX];        //                      3.2KB
    __shared__ float  s_prob[TILE_N][NC];   // softmax probs        8KB

    const int tid  = threadIdx.x;
    const int lane = tid & 31;
    const int warp = tid >> 5;
    const int n0   = blockIdx.x * TILE_N;
    const int n    = n0 + warp;

    // --- Stage raw targets ---
    const float4* tb4 = reinterpret_cast<const float4*>(tboxes);
    for (int m = tid; m < nt; m += THREADS) {
        s_t[m]   = tb4[m];
        s_lab[m] = labels[m];
    }

    // --- Softmax (warp handles its row; 8 classes/lane via 2x float4) ---
    float pcx = 0.f, pcy = 0.f, pw = 0.f, ph = 0.f;
    float px0 = 0.f, py0 = 0.f, px1 = 0.f, py1 = 0.f, pa = 0.f;
    if (n < n_rows) {
        const float4* lr4 = reinterpret_cast<const float4*>(logits + (size_t)n * NC);
        float4 a = lr4[lane];
        float4 b = lr4[lane + 32];
        float mx = fmaxf(fmaxf(fmaxf(a.x, a.y), fmaxf(a.z, a.w)),
                         fmaxf(fmaxf(b.x, b.y), fmaxf(b.z, b.w)));
        #pragma unroll
        for (int o = 16; o > 0; o >>= 1)
            mx = fmaxf(mx, __shfl_xor_sync(0xffffffffu, mx, o));

        a.x = __expf(a.x - mx); a.y = __expf(a.y - mx);
        a.z = __expf(a.z - mx); a.w = __expf(a.w - mx);
        b.x = __expf(b.x - mx); b.y = __expf(b.y - mx);
        b.z = __expf(b.z - mx); b.w = __expf(b.w - mx);
        float sum = (a.x + a.y) + (a.z + a.w) + (b.x + b.y) + (b.z + b.w);
        #pragma unroll
        for (int o = 16; o > 0; o >>= 1)
            sum += __shfl_xor_sync(0xffffffffu, sum, o);
        float inv = __fdividef(1.0f, sum);
        a.x *= inv; a.y *= inv; a.z *= inv; a.w *= inv;
        b.x *= inv; b.y *= inv; b.z *= inv; b.w *= inv;
        float4* pr = reinterpret_cast<float4*>(s_prob[warp]);
        pr[lane]      = a;
        pr[lane + 32] = b;

        // pred box into registers (all lanes load same addr -> broadcast)
        float4 pb = reinterpret_cast<const float4*>(pboxes)[n];
        pcx = pb.x; pcy = pb.y; pw = pb.z; ph = pb.w;
        float hw = 0.5f * pw, hh = 0.5f * ph;
        px0 = pcx - hw; py0 = pcy - hh;
        px1 = pcx + hw; py1 = pcy + hh;
        pa  = pw * ph;
    }
    __syncthreads();

    if (n >= n_rows) return;

    const float* probrow = s_prob[warp];
    float4* orow4 = reinterpret_cast<float4*>(out + (size_t)n * nt);
    const int4* lab4 = reinterpret_cast<const int4*>(s_lab);
    const int nt4 = nt >> 2;

    for (int q = lane; q < nt4; q += 32) {
        float4 t0 = s_t[4 * q + 0];
        float4 t1 = s_t[4 * q + 1];
        float4 t2 = s_t[4 * q + 2];
        float4 t3 = s_t[4 * q + 3];
        int4 lb = lab4[q];
        float p0 = probrow[lb.x];
        float p1 = probrow[lb.y];
        float p2 = probrow[lb.z];
        float p3 = probrow[lb.w];

        float4 r;
        r.x = pair_cost(pcx, pcy, pw, ph, px0, py0, px1, py1, pa, t0, p0);
        r.y = pair_cost(pcx, pcy, pw, ph, px0, py0, px1, py1, pa, t1, p1);
        r.z = pair_cost(pcx, pcy, pw, ph, px0, py0, px1, py1, pa, t2, p2);
        r.w = pair_cost(pcx, pcy, pw, ph, px0, py0, px1, py1, pa, t3, p3);
        orow4[q] = r;
    }

    // tail for nt % 4 != 0 (not hit for nt=800)
    for (int m = (nt4 << 2) + lane; m < nt; m += 32) {
        float4 t = s_t[m];
        float p = probrow[s_lab[m]];
        out[(size_t)n * nt + m] =
            pair_cost(pcx, pcy, pw, ph, px0, py0, px1, py1, pa, t, p);
    }
}

extern "C" void kernel_launch(void* const* d_in, const int* in_sizes, int n_in,
                              void* d_out, int out_size)
{
    const float* logits = (const float*)d_in[0];
    const float* pboxes = (const float*)d_in[1];
    const int*   labels = (const int*)  d_in[2];
    const float* tboxes = (const float*)d_in[3];
    float*       out    = (float*)d_out;

    const int n_rows = in_sizes[1] / 4;   // 14400
    const int nt     = in_sizes[2];       // 800

    const int blocks = (n_rows + TILE_N - 1) / TILE_N;
    matcher_cost_kernel<<<blocks, THREADS>>>(logits, pboxes, labels, tboxes,
                                             out, n_rows, nt);
}

// round 4
// speedup vs baseline: 2.4511x; 1.2772x over previous
#include <cuda_runtime.h>
#include <cuda_bf16.h>

// HungarianMatcher cost tensor C[16,900,800], nc=256.
// R3: targets live in REGISTERS (4 per thread, loaded once per block); thread
// loops over the 8 query rows of its tile. Smem traffic per output drops from
// ~24B (R2: target float4 + label + gather) to ~5B (prob gather + broadcast
// pred). Attacks the L1=73% bottleneck seen in R2's profile.

constexpr int NC      = 256;
constexpr int TILE_R  = 8;     // query rows per block (one softmax warp each)
constexpr int THREADS = 256;
constexpr int NT_PER  = 4;     // targets per thread (800 = 200 threads * 4)

constexpr float EPS = 1e-7f;

__global__ __launch_bounds__(THREADS, 2)
void matcher_cost_kernel(const float* __restrict__ logits,   // [N, NC]
                         const float* __restrict__ pboxes,   // [N, 4]
                         const int*   __restrict__ labels,   // [nt]
                         const float* __restrict__ tboxes,   // [nt, 4]
                         float*       __restrict__ out,      // [N, nt]
                         int n_rows, int nt)
{
    __shared__ float  s_prob[TILE_R][NC];   // softmax probs, 8KB
    __shared__ float4 s_pred[TILE_R][3];    // {cx,cy,w,h},{x0,y0,x1,y1},{area,-,-,-}

    const int tid  = threadIdx.x;
    const int lane = tid & 31;
    const int warp = tid >> 5;
    const int n0   = blockIdx.x * TILE_R;

    // --- Load this thread's 4 targets into registers (once per block) ---
    const int  mbase = tid * NT_PER;
    const bool act   = (mbase + NT_PER) <= nt;   // nt=800 -> threads 0..199 active
    float tcx[NT_PER], tcy[NT_PER], tw[NT_PER], th[NT_PER];
    float tx0[NT_PER], ty0[NT_PER], tx1[NT_PER], ty1[NT_PER], ta[NT_PER];
    int   lab[NT_PER];
    if (act) {
        const float4* tb4 = reinterpret_cast<const float4*>(tboxes);
        int4 lb = reinterpret_cast<const int4*>(labels)[tid];
        lab[0] = lb.x; lab[1] = lb.y; lab[2] = lb.z; lab[3] = lb.w;
        #pragma unroll
        for (int j = 0; j < NT_PER; j++) {
            float4 b = tb4[mbase + j];
            tcx[j] = b.x; tcy[j] = b.y; tw[j] = b.z; th[j] = b.w;
            float hw = 0.5f * b.z, hh = 0.5f * b.w;
            tx0[j] = b.x - hw; ty0[j] = b.y - hh;
            tx1[j] = b.x + hw; ty1[j] = b.y + hh;
            ta[j]  = b.z * b.w;
        }
    }

    // --- Softmax: warp w owns row n0+w (256 classes, 8/lane via 2x float4) ---
    const int n = n0 + warp;
    if (n < n_rows) {
        const float4* lr4 = reinterpret_cast<const float4*>(logits + (size_t)n * NC);
        float4 a = lr4[lane];
        float4 b = lr4[lane + 32];
        float mx = fmaxf(fmaxf(fmaxf(a.x, a.y), fmaxf(a.z, a.w)),
                         fmaxf(fmaxf(b.x, b.y), fmaxf(b.z, b.w)));
        #pragma unroll
        for (int o = 16; o > 0; o >>= 1)
            mx = fmaxf(mx, __shfl_xor_sync(0xffffffffu, mx, o));

        a.x = __expf(a.x - mx); a.y = __expf(a.y - mx);
        a.z = __expf(a.z - mx); a.w = __expf(a.w - mx);
        b.x = __expf(b.x - mx); b.y = __expf(b.y - mx);
        b.z = __expf(b.z - mx); b.w = __expf(b.w - mx);
        float sum = (a.x + a.y) + (a.z + a.w) + (b.x + b.y) + (b.z + b.w);
        #pragma unroll
        for (int o = 16; o > 0; o >>= 1)
            sum += __shfl_xor_sync(0xffffffffu, sum, o);
        float inv = __fdividef(1.0f, sum);
        a.x *= inv; a.y *= inv; a.z *= inv; a.w *= inv;
        b.x *= inv; b.y *= inv; b.z *= inv; b.w *= inv;
        float4* pr = reinterpret_cast<float4*>(s_prob[warp]);
        pr[lane]      = a;
        pr[lane + 32] = b;

        if (lane == 0) {
            float4 pb = reinterpret_cast<const float4*>(pboxes)[n];
            float hw = 0.5f * pb.z, hh = 0.5f * pb.w;
            s_pred[warp][0] = pb;
            s_pred[warp][1] = make_float4(pb.x - hw, pb.y - hh, pb.x + hw, pb.y + hh);
            s_pred[warp][2] = make_float4(pb.z * pb.w, 0.f, 0.f, 0.f);
        }
    }
    __syncthreads();

    // --- Main loop: rows of the tile; targets from registers ---
    if (act) {
        const int rmax = min(TILE_R, n_rows - n0);
        for (int r = 0; r < rmax; r++) {
            float4 pc = s_pred[r][0];           // broadcast LDS.128
            float4 px = s_pred[r][1];
            float  pa = s_pred[r][2].x;
            const float* __restrict__ pr = s_prob[r];

            float res[NT_PER];
            #pragma unroll
            for (int j = 0; j < NT_PER; j++) {
                float p = pr[lab[j]];

                float l1 = fabsf(pc.x - tcx[j]) + fabsf(pc.y - tcy[j])
                         + fabsf(pc.z - tw[j])  + fabsf(pc.w - th[j]);

                float ix = fminf(px.z, tx1[j]) - fmaxf(px.x, tx0[j]);
                float iy = fminf(px.w, ty1[j]) - fmaxf(px.y, ty0[j]);
                float inter = fmaxf(ix, 0.0f) * fmaxf(iy, 0.0f);
                float uni   = pa + ta[j] - inter;
                float iou   = __fdividef(inter, uni + EPS);

                float cx = fmaxf(px.z, tx1[j]) - fminf(px.x, tx0[j]);
                float cy = fmaxf(px.w, ty1[j]) - fminf(px.y, ty0[j]);
                float ca = cx * cy;
                float giou = iou - __fdividef(ca - uni, ca + EPS);

                res[j] = 5.0f * l1 - p - 2.0f * giou;
            }
            float4 r4 = make_float4(res[0], res[1], res[2], res[3]);
            *reinterpret_cast<float4*>(out + (size_t)(n0 + r) * nt + mbase) = r4;
        }
    } else if (mbase < nt) {
        // generic tail (not hit for nt=800): scalar per-target handling
        const int rmax = min(TILE_R, n_rows - n0);
        for (int j = 0; j < NT_PER && mbase + j < nt; j++) {
            int m = mbase + j;
            float4 b = reinterpret_cast<const float4*>(tboxes)[m];
            int   lb = labels[m];
            float hw = 0.5f * b.z, hh = 0.5f * b.w;
            float bx0 = b.x - hw, by0 = b.y - hh, bx1 = b.x + hw, by1 = b.y + hh;
            float bar = b.z * b.w;
            for (int r = 0; r < rmax; r++) {
                float4 pc = s_pred[r][0];
                float4 px = s_pred[r][1];
                float  pa = s_pred[r][2].x;
                float p = s_prob[r][lb];
                float l1 = fabsf(pc.x - b.x) + fabsf(pc.y - b.y)
                         + fabsf(pc.z - b.z) + fabsf(pc.w - b.w);
                float ix = fminf(px.z, bx1) - fmaxf(px.x, bx0);
                float iy = fminf(px.w, by1) - fmaxf(px.y, by0);
                float inter = fmaxf(ix, 0.0f) * fmaxf(iy, 0.0f);
                float uni = pa + bar - inter;
                float iou = __fdividef(inter, uni + EPS);
                float cx = fmaxf(px.z, bx1) - fminf(px.x, bx0);
                float cy = fmaxf(px.w, by1) - fminf(px.y, by0);
                float ca = cx * cy;
                float giou = iou - __fdividef(ca - uni, ca + EPS);
                out[(size_t)(n0 + r) * nt + m] = 5.0f * l1 - p - 2.0f * giou;
            }
        }
    }
}

extern "C" void kernel_launch(void* const* d_in, const int* in_sizes, int n_in,
                              void* d_out, int out_size)
{
    const float* logits = (const float*)d_in[0];
    const float* pboxes = (const float*)d_in[1];
    const int*   labels = (const int*)  d_in[2];
    const float* tboxes = (const float*)d_in[3];
    float*       out    = (float*)d_out;

    const int n_rows = in_sizes[1] / 4;   // 14400
    const int nt     = in_sizes[2];       // 800

    const int blocks = (n_rows + TILE_R - 1) / TILE_R;
    matcher_cost_kernel<<<blocks, THREADS>>>(logits, pboxes, labels, tboxes,
                                             out, n_rows, nt);
}

// round 5
// speedup vs baseline: 2.9286x; 1.1948x over previous
#include <cuda_runtime.h>
#include <cuda_bf16.h>

// HungarianMatcher cost tensor C[16,900,800], nc=256.
// R4: issue-bound optimization. 6 regs/target (derive xyxy in-loop) to reach
// 3 blocks/SM; enclosing-box via min/max sum identity; single combined
// division for giou; fully unrolled 8-row loop.

constexpr int NC      = 256;
constexpr int TILE_R  = 8;     // query rows per block
constexpr int THREADS = 256;
constexpr int NT_PER  = 4;     // targets per thread (800 = 200 threads * 4)

constexpr float EPS = 1e-7f;

__global__ __launch_bounds__(THREADS, 3)
void matcher_cost_kernel(const float* __restrict__ logits,   // [N, NC]
                         const float* __restrict__ pboxes,   // [N, 4]
                         const int*   __restrict__ labels,   // [nt]
                         const float* __restrict__ tboxes,   // [nt, 4]
                         float*       __restrict__ out,      // [N, nt]
                         int n_rows, int nt)
{
    __shared__ float  s_prob[TILE_R][NC];   // softmax probs, 8KB
    __shared__ float4 s_pred[TILE_R][3];    // {cx,cy,w,h},{x0,y0,x1,y1},{area,..}

    const int tid  = threadIdx.x;
    const int lane = tid & 31;
    const int warp = tid >> 5;
    const int n0   = blockIdx.x * TILE_R;

    // --- This thread's 4 targets -> registers (6 per target) ---
    const int  mbase = tid * NT_PER;
    const bool act   = (mbase + NT_PER) <= nt;   // threads 0..199 for nt=800
    float tcx[NT_PER], tcy[NT_PER], thw[NT_PER], thh[NT_PER], ta[NT_PER];
    int   lob[NT_PER];                            // label byte offsets
    if (act) {
        const float4* tb4 = reinterpret_cast<const float4*>(tboxes);
        int4 lb = reinterpret_cast<const int4*>(labels)[tid];
        lob[0] = lb.x * 4; lob[1] = lb.y * 4; lob[2] = lb.z * 4; lob[3] = lb.w * 4;
        #pragma unroll
        for (int j = 0; j < NT_PER; j++) {
            float4 b = tb4[mbase + j];
            tcx[j] = b.x; tcy[j] = b.y;
            thw[j] = 0.5f * b.z; thh[j] = 0.5f * b.w;
            ta[j]  = b.z * b.w;
        }
    }

    // --- Softmax: warp w owns row n0+w (256 classes, 8/lane) ---
    const int n = n0 + warp;
    if (n < n_rows) {
        const float4* lr4 = reinterpret_cast<const float4*>(logits + (size_t)n * NC);
        float4 a = lr4[lane];
        float4 b = lr4[lane + 32];
        float mx = fmaxf(fmaxf(fmaxf(a.x, a.y), fmaxf(a.z, a.w)),
                         fmaxf(fmaxf(b.x, b.y), fmaxf(b.z, b.w)));
        #pragma unroll
        for (int o = 16; o > 0; o >>= 1)
            mx = fmaxf(mx, __shfl_xor_sync(0xffffffffu, mx, o));
        a.x = __expf(a.x - mx); a.y = __expf(a.y - mx);
        a.z = __expf(a.z - mx); a.w = __expf(a.w - mx);
        b.x = __expf(b.x - mx); b.y = __expf(b.y - mx);
        b.z = __expf(b.z - mx); b.w = __expf(b.w - mx);
        float sum = (a.x + a.y) + (a.z + a.w) + (b.x + b.y) + (b.z + b.w);
        #pragma unroll
        for (int o = 16; o > 0; o >>= 1)
            sum += __shfl_xor_sync(0xffffffffu, sum, o);
        float inv = __fdividef(1.0f, sum);
        a.x *= inv; a.y *= inv; a.z *= inv; a.w *= inv;
        b.x *= inv; b.y *= inv; b.z *= inv; b.w *= inv;
        float4* pr = reinterpret_cast<float4*>(s_prob[warp]);
        pr[lane]      = a;
        pr[lane + 32] = b;

        if (lane == 0) {
            float4 pb = reinterpret_cast<const float4*>(pboxes)[n];
            float hw = 0.5f * pb.z, hh = 0.5f * pb.w;
            s_pred[warp][0] = pb;
            s_pred[warp][1] = make_float4(pb.x - hw, pb.y - hh, pb.x + hw, pb.y + hh);
            s_pred[warp][2] = make_float4(pb.z * pb.w, 0.f, 0.f, 0.f);
        }
    }
    __syncthreads();

    if (!act) {
        // generic tail (nt not multiple of 4; unused for nt=800)
        if (mbase < nt) {
            const int rmax = min(TILE_R, n_rows - n0);
            for (int j = 0; j < NT_PER && mbase + j < nt; j++) {
                int m = mbase + j;
                float4 b = reinterpret_cast<const float4*>(tboxes)[m];
                int lb = labels[m];
                float hw = 0.5f * b.z, hh = 0.5f * b.w;
                float bx0 = b.x - hw, by0 = b.y - hh, bx1 = b.x + hw, by1 = b.y + hh;
                float bar = b.z * b.w;
                for (int r = 0; r < rmax; r++) {
                    float4 pc = s_pred[r][0];
                    float4 px = s_pred[r][1];
                    float  pa = s_pred[r][2].x;
                    float p = s_prob[r][lb];
                    float l1 = fabsf(pc.x - b.x) + fabsf(pc.y - b.y)
                             + fabsf(pc.z - b.z) + fabsf(pc.w - b.w);
                    float ix = fminf(px.z, bx1) - fmaxf(px.x, bx0);
                    float iy = fminf(px.w, by1) - fmaxf(px.y, by0);
                    float inter = fmaxf(ix, 0.f) * fmaxf(iy, 0.f);
                    float uni = pa + bar - inter;
                    float iou = __fdividef(inter, uni + EPS);
                    float cxv = fmaxf(px.z, bx1) - fminf(px.x, bx0);
                    float cyv = fmaxf(px.w, by1) - fminf(px.y, by0);
                    float ca = cxv * cyv;
                    float giou = iou - __fdividef(ca - uni, ca + EPS);
                    out[(size_t)(n0 + r) * nt + m] = 5.f * l1 - p - 2.f * giou;
                }
            }
        }
        return;
    }

    // --- Fast path: fully unrolled over 8 rows, targets in registers ---
    float* orow = out + (size_t)n0 * nt + mbase;
    const int rmax = n_rows - n0;   // >= TILE_R except possibly last block

    #pragma unroll
    for (int r = 0; r < TILE_R; r++) {
        if (r >= rmax) break;
        const float4 pc = s_pred[r][0];   // broadcast LDS.128
        const float4 px = s_pred[r][1];
        const float  pa = s_pred[r][2].x;
        const char* prb = reinterpret_cast<const char*>(s_prob[r]);

        float res[NT_PER];
        #pragma unroll
        for (int j = 0; j < NT_PER; j++) {
            float p = *reinterpret_cast<const float*>(prb + lob[j]);

            float tx0 = tcx[j] - thw[j], tx1 = tcx[j] + thw[j];
            float ty0 = tcy[j] - thh[j], ty1 = tcy[j] + thh[j];

            // L1: center terms direct, width terms via FFMA against half-width
            float l1 = fabsf(pc.x - tcx[j]) + fabsf(pc.y - tcy[j])
                     + fabsf(fmaf(-2.f, thw[j], pc.z))
                     + fabsf(fmaf(-2.f, thh[j], pc.w));

            float ix = fminf(px.z, tx1) - fmaxf(px.x, tx0);
            float iy = fminf(px.w, ty1) - fmaxf(px.y, ty0);
            float inter = fmaxf(ix, 0.f) * fmaxf(iy, 0.f);
            float uni   = pa + ta[j] - inter;

            // enclosing box via identity: max(a,b)+min(a,b)=a+b
            // cx = (pw + tw) - ix, tw = 2*thw
            float cxv = fmaf(2.f, thw[j], pc.z) - ix;
            float cyv = fmaf(2.f, thh[j], pc.w) - iy;
            float ca  = cxv * cyv;

            // giou = inter/u - (ca-uni)/c  ==  (inter*c - (ca-uni)*u) / (u*c)
            float u = uni + EPS;
            float c = ca + EPS;
            float num = fmaf(-(ca - uni), u, inter * c);
            float giou = __fdividef(num, u * c);

            float rr = fmaf(5.f, l1, -p);
            res[j] = fmaf(-2.f, giou, rr);
        }
        *reinterpret_cast<float4*>(orow) = make_float4(res[0], res[1], res[2], res[3]);
        orow += nt;
    }
}

extern "C" void kernel_launch(void* const* d_in, const int* in_sizes, int n_in,
                              void* d_out, int out_size)
{
    const float* logits = (const float*)d_in[0];
    const float* pboxes = (const float*)d_in[1];
    const int*   labels = (const int*)  d_in[2];
    const float* tboxes = (const float*)d_in[3];
    float*       out    = (float*)d_out;

    const int n_rows = in_sizes[1] / 4;   // 14400
    const int nt     = in_sizes[2];       // 800

    const int blocks = (n_rows + TILE_R - 1) / TILE_R;
    matcher_cost_kernel<<<blocks, THREADS>>>(logits, pboxes, labels, tboxes,
                                             out, n_rows, nt);
}